// round 8
// baseline (speedup 1.0000x reference)
#include <cuda_runtime.h>
#include <cuda_bf16.h>
#include <cstdint>

#define NB     4
#define LDEC   4096
#define LENC   4096
#define DM     512
#define NH     8
#define DH     64
#define UPART  45
#define NTOP   45
#define BH     (NB*NH)
#define GM     (NB*LDEC)   // 16384 rows for all projections
#define NSPLIT 16
#define KSEG   (LENC/NSPLIT)  // 256
#define QPW    12             // ceil(45/4) queries per warp in attn kernel
#define FULL   0xffffffffu

// ------------------------- scratch (device globals; no cudaMalloc) -----------
__device__ float g_Q[(size_t)GM * DM];        // 33.5 MB
__device__ float g_K[(size_t)GM * DM];        // 33.5 MB
__device__ float g_V[(size_t)GM * DM];        // 33.5 MB
__device__ float g_M[BH * LDEC];              // 0.5 MB
__device__ int   g_top[BH * NTOP];
__device__ float g_pm[BH * NSPLIT * NTOP];
__device__ float g_pl[BH * NSPLIT * NTOP];
__device__ float g_pacc[(size_t)BH * NSPLIT * NTOP * DH];  // 5.9 MB
__device__ float g_upd[BH * NTOP * DH];
__device__ float g_vpart[NB * 32 * DM];
__device__ float g_vmean[NB * DM];            // unnormalized sum (scale by 1/LENC at use)
__device__ float g_base[NB * DM];

// --------- 1) fused fp32 QKV GEMM: C_z = A_z(16384x512) @ W_z(512x512) + b_z --
// 128x128 tile, BK=8, 8x8 per thread, 256 threads, double-buffered smem.
// blockIdx.z: 0 -> Q (input x), 1 -> K (context), 2 -> V (context).
// One launch of 1536 CTAs instead of 3x512 -> one wave tail instead of three.
__global__ __launch_bounds__(256) void qkv_gemm_kernel(
    const float* __restrict__ x, const float* __restrict__ context,
    const float* __restrict__ Wq, const float* __restrict__ Wk,
    const float* __restrict__ Wv,
    const float* __restrict__ bq, const float* __restrict__ bk,
    const float* __restrict__ bv)
{
    const int z = blockIdx.z;
    const float* A    = (z == 0) ? x  : context;
    const float* W    = (z == 0) ? Wq : (z == 1) ? Wk : Wv;
    const float* bias = (z == 0) ? bq : (z == 1) ? bk : bv;
    float* C          = (z == 0) ? g_Q : (z == 1) ? g_K : g_V;

    __shared__ float As[2][8][128];
    __shared__ float Bs[2][8][128];
    const int tid = threadIdx.x;
    const int bn = blockIdx.x;   // 0..3   (N/128)
    const int bm = blockIdx.y;   // 0..127 (M/128)

    const int arow = tid >> 1;          // 0..127
    const int acol = (tid & 1) * 4;     // 0 or 4
    const int brow = tid >> 5;          // 0..7
    const int bcol = (tid & 31) * 4;    // 0..124
    const int ty = tid >> 4, tx = tid & 15;

    const float* Aptr = A + (size_t)(bm * 128 + arow) * DM + acol;
    const float* Wptr = W + (size_t)brow * DM + bn * 128 + bcol;

    float acc[8][8];
#pragma unroll
    for (int i = 0; i < 8; i++)
#pragma unroll
        for (int j = 0; j < 8; j++) acc[i][j] = 0.f;

    // prologue: load k0 = 0 into buffer 0
    {
        float4 av = *(const float4*)(Aptr);
        float4 bv4 = *(const float4*)(Wptr);
        As[0][acol + 0][arow] = av.x;
        As[0][acol + 1][arow] = av.y;
        As[0][acol + 2][arow] = av.z;
        As[0][acol + 3][arow] = av.w;
        *(float4*)&Bs[0][brow][bcol] = bv4;
    }
    __syncthreads();

    int buf = 0;
    for (int k0 = 0; k0 < DM; k0 += 8) {
        // prefetch next K-stage into registers (overlaps with compute below)
        float4 av, bv4;
        const bool has_next = (k0 + 8) < DM;
        if (has_next) {
            av  = *(const float4*)(Aptr + (k0 + 8));
            bv4 = *(const float4*)(Wptr + (size_t)(k0 + 8) * DM);
        }
#pragma unroll
        for (int k = 0; k < 8; k++) {
            float4 a0 = *(const float4*)&As[buf][k][ty * 8];
            float4 a1 = *(const float4*)&As[buf][k][ty * 8 + 4];
            float4 b0 = *(const float4*)&Bs[buf][k][tx * 8];
            float4 b1 = *(const float4*)&Bs[buf][k][tx * 8 + 4];
            float ra[8] = {a0.x, a0.y, a0.z, a0.w, a1.x, a1.y, a1.z, a1.w};
            float rb[8] = {b0.x, b0.y, b0.z, b0.w, b1.x, b1.y, b1.z, b1.w};
#pragma unroll
            for (int i = 0; i < 8; i++)
#pragma unroll
                for (int j = 0; j < 8; j++)
                    acc[i][j] = fmaf(ra[i], rb[j], acc[i][j]);
        }
        if (has_next) {
            const int nb = buf ^ 1;
            As[nb][acol + 0][arow] = av.x;
            As[nb][acol + 1][arow] = av.y;
            As[nb][acol + 2][arow] = av.z;
            As[nb][acol + 3][arow] = av.w;
            *(float4*)&Bs[nb][brow][bcol] = bv4;
            __syncthreads();
            buf = nb;
        }
    }

#pragma unroll
    for (int i = 0; i < 8; i++) {
        const int row = bm * 128 + ty * 8 + i;
#pragma unroll
        for (int j = 0; j < 8; j += 4) {
            const int col = bn * 128 + tx * 8 + j;
            float4 o;
            o.x = acc[i][j + 0] + bias[col + 0];
            o.y = acc[i][j + 1] + bias[col + 1];
            o.z = acc[i][j + 2] + bias[col + 2];
            o.w = acc[i][j + 3] + bias[col + 3];
            *(float4*)(C + (size_t)row * DM + col) = o;
        }
    }
}

// ------------------------- 2) sampled scores -> M metric ---------------------
// grid: NB*LDEC blocks, 256 threads (warp w = head w)
__global__ __launch_bounds__(256) void sample_score_kernel(const int* __restrict__ sidx)
{
    const int bl = blockIdx.x;
    const int b = bl >> 12;
    const int l = bl & 4095;
    const int w = threadIdx.x >> 5;
    const int lane = threadIdx.x & 31;

    __shared__ int ss[UPART];
    if (threadIdx.x < UPART) ss[threadIdx.x] = sidx[l * UPART + threadIdx.x];
    __syncthreads();

    const float2 qv = ((const float2*)(g_Q + (size_t)bl * DM + w * DH))[lane];
    float mmax = -1e30f, msum = 0.f;
    for (int u = 0; u < UPART; u++) {
        const float2 kv = ((const float2*)(g_K + (size_t)(b * LENC + ss[u]) * DM + w * DH))[lane];
        float v = qv.x * kv.x + qv.y * kv.y;
#pragma unroll
        for (int o = 16; o; o >>= 1) v += __shfl_xor_sync(FULL, v, o);
        mmax = fmaxf(mmax, v);
        msum += v;
    }
    if (lane == 0)
        g_M[((b * NH + w) << 12) + l] = mmax - msum * (1.0f / (float)LENC);
}

// ------------------------- 3) top-45 per (b,h) -------------------------------
__global__ __launch_bounds__(256) void topk_kernel()
{
    const int bh = blockIdx.x;
    const float* Mrow = g_M + bh * LDEC;
    __shared__ float vals[LDEC];
    __shared__ float rv[256];
    __shared__ int ri[256];
    const int tid = threadIdx.x;
    for (int i = tid; i < LDEC; i += 256) vals[i] = Mrow[i];
    __syncthreads();
    for (int t = 0; t < NTOP; t++) {
        float bv = -1e30f; int bi = LDEC;
        for (int i = tid; i < LDEC; i += 256) {
            const float v = vals[i];
            if (v > bv || (v == bv && i < bi)) { bv = v; bi = i; }
        }
        rv[tid] = bv; ri[tid] = bi;
        __syncthreads();
        for (int s = 128; s; s >>= 1) {
            if (tid < s) {
                const float ov = rv[tid + s]; const int oi = ri[tid + s];
                if (ov > rv[tid] || (ov == rv[tid] && oi < ri[tid])) { rv[tid] = ov; ri[tid] = oi; }
            }
            __syncthreads();
        }
        if (tid == 0) {
            g_top[bh * NTOP + t] = ri[0];
            vals[ri[0]] = -1e30f;
        }
        __syncthreads();
    }
}

// ------------------------- 4) sparse attention, split-K partials -------------
// grid (BH, NSPLIT), 128 threads (4 warps), online softmax per query per warp
__global__ __launch_bounds__(128) void attn_partial_kernel()
{
    const int bh = blockIdx.x;
    const int sp = blockIdx.y;
    const int b = bh >> 3, h = bh & 7;
    const int tid = threadIdx.x, w = tid >> 5, lane = tid & 31;

    __shared__ float Qs[NTOP][DH];
    __shared__ float Ks[32][65];
    __shared__ float Vs[32][65];

    for (int idx = tid; idx < NTOP * 16; idx += 128) {
        const int u = idx >> 4, c4 = idx & 15;
        const int qi = g_top[bh * NTOP + u];
        *(float4*)&Qs[u][c4 * 4] =
            *(const float4*)(g_Q + (size_t)(b * LDEC + qi) * DM + h * DH + c4 * 4);
    }
    __syncthreads();

    float m[QPW], lsum[QPW], acc0[QPW], acc1[QPW];
#pragma unroll
    for (int i = 0; i < QPW; i++) { m[i] = -1e30f; lsum[i] = 0.f; acc0[i] = 0.f; acc1[i] = 0.f; }

    const int kbase = sp * KSEG;
    for (int kt = 0; kt < KSEG; kt += 32) {
        for (int idx = tid; idx < 32 * 16; idx += 128) {
            const int r = idx >> 4, c4 = idx & 15;
            const size_t off = (size_t)(b * LENC + kbase + kt + r) * DM + h * DH + c4 * 4;
            // Ks/Vs rows have stride 65 floats (260B) -> float4 STS would be
            // misaligned on odd rows. Load gmem as float4, store 4 scalars.
            const float4 kv = *(const float4*)(g_K + off);
            const float4 vv = *(const float4*)(g_V + off);
            Ks[r][c4 * 4 + 0] = kv.x; Ks[r][c4 * 4 + 1] = kv.y;
            Ks[r][c4 * 4 + 2] = kv.z; Ks[r][c4 * 4 + 3] = kv.w;
            Vs[r][c4 * 4 + 0] = vv.x; Vs[r][c4 * 4 + 1] = vv.y;
            Vs[r][c4 * 4 + 2] = vv.z; Vs[r][c4 * 4 + 3] = vv.w;
        }
        __syncthreads();
#pragma unroll
        for (int qq = 0; qq < QPW; qq++) {
            const int u = w + qq * 4;
            if (u < NTOP) {
                float s = 0.f;
#pragma unroll
                for (int d = 0; d < DH; d++) s = fmaf(Qs[u][d], Ks[lane][d], s);
                s *= 0.125f;   // 1/sqrt(64)
                float tm = s;
#pragma unroll
                for (int o = 16; o; o >>= 1) tm = fmaxf(tm, __shfl_xor_sync(FULL, tm, o));
                const float nm = fmaxf(m[qq], tm);
                const float scale = __expf(m[qq] - nm);
                const float p = __expf(s - nm);
                float ps = p;
#pragma unroll
                for (int o = 16; o; o >>= 1) ps += __shfl_xor_sync(FULL, ps, o);
                lsum[qq] = lsum[qq] * scale + ps;
                acc0[qq] *= scale; acc1[qq] *= scale;
                m[qq] = nm;
#pragma unroll
                for (int j = 0; j < 32; j++) {
                    const float pj = __shfl_sync(FULL, p, j);
                    acc0[qq] = fmaf(pj, Vs[j][lane], acc0[qq]);
                    acc1[qq] = fmaf(pj, Vs[j][lane + 32], acc1[qq]);
                }
            }
        }
        __syncthreads();
    }
#pragma unroll
    for (int qq = 0; qq < QPW; qq++) {
        const int u = w + qq * 4;
        if (u < NTOP) {
            const int base = (bh * NSPLIT + sp) * NTOP + u;
            if (lane == 0) { g_pm[base] = m[qq]; g_pl[base] = lsum[qq]; }
            g_pacc[(size_t)base * DH + lane]      = acc0[qq];
            g_pacc[(size_t)base * DH + lane + 32] = acc1[qq];
        }
    }
}

// ------------------------- 5) combine split-K partials -----------------------
__global__ __launch_bounds__(256) void attn_combine_kernel()
{
    const int bh = blockIdx.x;
    const int w = threadIdx.x >> 5, lane = threadIdx.x & 31;
    for (int u = w; u < NTOP; u += 8) {
        float mg = -1e30f;
        if (lane < NSPLIT) mg = g_pm[(bh * NSPLIT + lane) * NTOP + u];
#pragma unroll
        for (int o = 16; o; o >>= 1) mg = fmaxf(mg, __shfl_xor_sync(FULL, mg, o));
        float lg = 0.f;
        if (lane < NSPLIT)
            lg = g_pl[(bh * NSPLIT + lane) * NTOP + u] *
                 __expf(g_pm[(bh * NSPLIT + lane) * NTOP + u] - mg);
#pragma unroll
        for (int o = 16; o; o >>= 1) lg += __shfl_xor_sync(FULL, lg, o);
        float a0 = 0.f, a1 = 0.f;
        for (int s = 0; s < NSPLIT; s++) {
            const int base = (bh * NSPLIT + s) * NTOP + u;
            const float wgt = __expf(g_pm[base] - mg);
            a0 = fmaf(wgt, g_pacc[(size_t)base * DH + lane], a0);
            a1 = fmaf(wgt, g_pacc[(size_t)base * DH + lane + 32], a1);
        }
        const float inv = 1.0f / lg;
        g_upd[(bh * NTOP + u) * DH + lane]      = a0 * inv;
        g_upd[(bh * NTOP + u) * DH + lane + 32] = a1 * inv;
    }
}

// ------------------------- 6) V column sums (deterministic 2-stage) ----------
__global__ __launch_bounds__(512) void vmean_part_kernel()
{
    const int b = blockIdx.x >> 5;
    const int chunk = blockIdx.x & 31;
    const int c = threadIdx.x;
    const float* base = g_V + (size_t)(b * LENC + chunk * 128) * DM + c;
    float s = 0.f;
#pragma unroll 4
    for (int r = 0; r < 128; r++) s += base[(size_t)r * DM];
    g_vpart[blockIdx.x * DM + c] = s;
}

__global__ __launch_bounds__(512) void vmean_final_kernel()
{
    const int b = blockIdx.x;
    const int c = threadIdx.x;
    float s = 0.f;
#pragma unroll
    for (int k = 0; k < 32; k++) s += g_vpart[(b * 32 + k) * DM + c];
    g_vmean[b * DM + c] = s;
}

// ------------------------- 7) base row: (Vmean cat) @ Wo + bo ----------------
__global__ __launch_bounds__(512) void base_out_kernel(const float* __restrict__ Wo,
                                                       const float* __restrict__ bo)
{
    const int b = blockIdx.x;
    const int j = threadIdx.x;
    __shared__ float vm[DM];
    vm[j] = g_vmean[b * DM + j] * (1.0f / (float)LENC);
    __syncthreads();
    float acc = bo[j];
    for (int k = 0; k < DM; k++) acc = fmaf(vm[k], Wo[(size_t)k * DM + j], acc);
    g_base[b * DM + j] = acc;
}

// ------------------------- 8) broadcast-fill output --------------------------
__global__ __launch_bounds__(256) void fill_kernel(float* __restrict__ out)
{
    const size_t i = (size_t)blockIdx.x * 256 + threadIdx.x;  // float4 index
    const int j4 = (int)(i & 127);            // 128 float4 per row
    const size_t row = i >> 7;                // b*LDEC + l
    const int b = (int)(row >> 12);
    ((float4*)out)[i] = *(const float4*)&g_base[b * DM + j4 * 4];
}

// ------------------------- 9) rank-64 row corrections (per head, race-free) --
__global__ __launch_bounds__(256) void delta_kernel(int h, const float* __restrict__ Wo,
                                                    float* __restrict__ out)
{
    const int g = blockIdx.x;       // 0 .. NB*NTOP-1
    const int b = g / NTOP;
    const int u = g % NTOP;
    const int bh = b * NH + h;
    __shared__ float dv[DH];
    const int tid = threadIdx.x;
    if (tid < DH)
        dv[tid] = g_upd[(bh * NTOP + u) * DH + tid] -
                  g_vmean[b * DM + h * DH + tid] * (1.0f / (float)LENC);
    __syncthreads();
    const int row = g_top[bh * NTOP + u];
    float* orow = out + (size_t)(b * LDEC + row) * DM;
    for (int j = tid; j < DM; j += 256) {
        float acc = 0.f;
#pragma unroll
        for (int k = 0; k < DH; k++)
            acc = fmaf(dv[k], Wo[(size_t)(h * DH + k) * DM + j], acc);
        orow[j] += acc;   // distinct rows within one head -> no race
    }
}

// ------------------------- launcher ------------------------------------------
extern "C" void kernel_launch(void* const* d_in, const int* in_sizes, int n_in,
                              void* d_out, int out_size)
{
    const float* x       = (const float*)d_in[0];
    const float* context = (const float*)d_in[1];
    const float* Wq      = (const float*)d_in[2];
    const float* bq      = (const float*)d_in[3];
    const float* Wk      = (const float*)d_in[4];
    const float* bk      = (const float*)d_in[5];
    const float* Wv      = (const float*)d_in[6];
    const float* bv      = (const float*)d_in[7];
    const float* Wo      = (const float*)d_in[8];
    const float* bo      = (const float*)d_in[9];
    const int*   sidx    = (const int*)d_in[10];
    float* out = (float*)d_out;

    dim3 ggrid(DM / 128, GM / 128, 3);       // (4, 128, 3) -> 1536 CTAs, one tail
    qkv_gemm_kernel<<<ggrid, 256>>>(x, context, Wq, Wk, Wv, bq, bk, bv);

    sample_score_kernel<<<NB * LDEC, 256>>>(sidx);
    topk_kernel<<<BH, 256>>>();

    attn_partial_kernel<<<dim3(BH, NSPLIT), 128>>>();
    attn_combine_kernel<<<BH, 256>>>();

    vmean_part_kernel<<<NB * 32, 512>>>();
    vmean_final_kernel<<<NB, 512>>>();
    base_out_kernel<<<NB, 512>>>(Wo, bo);

    fill_kernel<<<(GM * DM / 4) / 256, 256>>>(out);
    for (int h = 0; h < NH; h++)
        delta_kernel<<<NB * NTOP, 256>>>(h, Wo, out);
}

// round 11
// speedup vs baseline: 1.1577x; 1.1577x over previous
#include <cuda_runtime.h>
#include <cuda_bf16.h>
#include <cstdint>

#define NB     4
#define LDEC   4096
#define LENC   4096
#define DM     512
#define NH     8
#define DH     64
#define UPART  45
#define NTOP   45
#define BH     (NB*NH)
#define GM     (NB*LDEC)   // 16384 rows for all projections
#define NSPLIT 16
#define KSEG   (LENC/NSPLIT)  // 256
#define QSPLIT 3
#define QPB    15             // queries per block in attn (3*15 = 45)
#define QPW2   4              // ceil(15/4) queries per warp
#define FULL   0xffffffffu

// ------------------------- scratch (device globals; no cudaMalloc) -----------
__device__ float g_Q[(size_t)GM * DM];        // 33.5 MB
__device__ float g_K[(size_t)GM * DM];        // 33.5 MB
__device__ float g_V[(size_t)GM * DM];        // 33.5 MB
__device__ float g_M[BH * LDEC];              // 0.5 MB
__device__ int   g_top[BH * NTOP];
__device__ float g_pm[BH * NSPLIT * NTOP];
__device__ float g_pl[BH * NSPLIT * NTOP];
__device__ float g_pacc[(size_t)BH * NSPLIT * NTOP * DH];  // 5.9 MB
__device__ float g_upd[BH * NTOP * DH];
__device__ float g_vpart[NB * 32 * DM];
__device__ float g_vmean[NB * DM];            // unnormalized sum (scale by 1/LENC at use)
__device__ float g_base[NB * DM];

// ------------------------- tf32 helpers --------------------------------------
__device__ __forceinline__ uint32_t f2tf32(float v) {
    uint32_t r;
    asm("cvt.rna.tf32.f32 %0, %1;" : "=r"(r) : "f"(v));
    return r;
}
__device__ __forceinline__ void tf32_split(float v, uint32_t& hi, uint32_t& lo) {
    hi = f2tf32(v);
    lo = f2tf32(v - __uint_as_float(hi));
}
__device__ __forceinline__ void mma8(float* c, const uint32_t* a, const uint32_t* b) {
    asm volatile(
        "mma.sync.aligned.m16n8k8.row.col.f32.tf32.tf32.f32 "
        "{%0,%1,%2,%3},{%4,%5,%6,%7},{%8,%9},{%0,%1,%2,%3};"
        : "+f"(c[0]), "+f"(c[1]), "+f"(c[2]), "+f"(c[3])
        : "r"(a[0]), "r"(a[1]), "r"(a[2]), "r"(a[3]), "r"(b[0]), "r"(b[1]));
}

// --------- 1) fused QKV GEMM via 3xTF32 tensor cores -------------------------
// C_z(16384x512) = A_z @ W_z + b_z.  Block tile 64(M)x128(N), BK=16, 4 warps
// (2Mx2N), warp tile 32x64 of m16n8k8 mma. fp32 operands split hi/lo tf32;
// 3 mmas per tile (hi*hi + hi*lo + lo*hi) -> ~2^-22 product error.
// blockIdx.z: 0 -> Q (x), 1 -> K (context), 2 -> V (context).
#define BKG   16
#define ASTR  72    // As row stride (64+8): frag LDS addr mod32 = 8k+m, bijective
#define BSTR  136   // Bs row stride (128+8): same property; 16B-aligned for f4
__global__ __launch_bounds__(128, 3) void qkv_gemm_tf32(
    const float* __restrict__ x, const float* __restrict__ context,
    const float* __restrict__ Wq, const float* __restrict__ Wk,
    const float* __restrict__ Wv,
    const float* __restrict__ bq, const float* __restrict__ bk,
    const float* __restrict__ bv)
{
    const int z = blockIdx.z;
    const float* A    = (z == 0) ? x  : context;
    const float* W    = (z == 0) ? Wq : (z == 1) ? Wk : Wv;
    const float* bias = (z == 0) ? bq : (z == 1) ? bk : bv;
    float* C          = (z == 0) ? g_Q : (z == 1) ? g_K : g_V;

    __shared__ float As[2][BKG][ASTR];
    __shared__ float Bs[2][BKG][BSTR];

    const int tid  = threadIdx.x;
    const int lane = tid & 31;
    const int wid  = tid >> 5;         // 0..3
    const int wm   = wid >> 1;         // 0..1 (M)
    const int wn   = wid & 1;          // 0..1 (N)
    const int gid  = lane >> 2;        // 0..7
    const int t4   = lane & 3;         // 0..3

    const int bn = blockIdx.x;         // 0..3   (N/128)
    const int bm = blockIdx.y;         // 0..255 (M/64)
    const int mG = bm * 64;
    const int nG = bn * 128;

    float acc[2][8][4];
#pragma unroll
    for (int i = 0; i < 2; i++)
#pragma unroll
        for (int j = 0; j < 8; j++)
#pragma unroll
            for (int k = 0; k < 4; k++) acc[i][j][k] = 0.f;

    // ---- prologue: stage k0 = 0 into buffer 0 ----
    {
#pragma unroll
        for (int j = 0; j < 2; j++) {                 // A: 256 float4 total
            const int f  = tid * 2 + j;
            const int ml = f >> 2;
            const int k4 = (f & 3) * 4;
            const float4 v = *(const float4*)(A + (size_t)(mG + ml) * DM + k4);
            As[0][k4 + 0][ml] = v.x; As[0][k4 + 1][ml] = v.y;
            As[0][k4 + 2][ml] = v.z; As[0][k4 + 3][ml] = v.w;
        }
#pragma unroll
        for (int j = 0; j < 4; j++) {                 // B: 512 float4 total
            const int g  = tid * 4 + j;
            const int kl = g >> 5;
            const int n4 = (g & 31) * 4;
            *(float4*)&Bs[0][kl][n4] =
                *(const float4*)(W + (size_t)kl * DM + nG + n4);
        }
    }
    __syncthreads();

    int buf = 0;
    for (int s = 0; s < DM / BKG; s++) {
        // prefetch next stage into registers
        float4 a_r[2], b_r[4];
        const bool has_next = (s + 1) < DM / BKG;
        if (has_next) {
            const int k0n = (s + 1) * BKG;
#pragma unroll
            for (int j = 0; j < 2; j++) {
                const int f  = tid * 2 + j;
                const int ml = f >> 2;
                const int k4 = (f & 3) * 4;
                a_r[j] = *(const float4*)(A + (size_t)(mG + ml) * DM + k0n + k4);
            }
#pragma unroll
            for (int j = 0; j < 4; j++) {
                const int g  = tid * 4 + j;
                const int kl = g >> 5;
                const int n4 = (g & 31) * 4;
                b_r[j] = *(const float4*)(W + (size_t)(k0n + kl) * DM + nG + n4);
            }
        }

        // compute 2 k8 sub-steps on current buffer
#pragma unroll
        for (int ks = 0; ks < BKG; ks += 8) {
            uint32_t bh[8][2], bl[8][2];
#pragma unroll
            for (int nt = 0; nt < 8; nt++) {
                const int nb = wn * 64 + nt * 8 + gid;
                tf32_split(Bs[buf][ks + t4][nb],     bh[nt][0], bl[nt][0]);
                tf32_split(Bs[buf][ks + t4 + 4][nb], bh[nt][1], bl[nt][1]);
            }
#pragma unroll
            for (int mt = 0; mt < 2; mt++) {
                const int mb = wm * 32 + mt * 16 + gid;
                uint32_t ah[4], al[4];
                tf32_split(As[buf][ks + t4][mb],         ah[0], al[0]);
                tf32_split(As[buf][ks + t4][mb + 8],     ah[1], al[1]);
                tf32_split(As[buf][ks + t4 + 4][mb],     ah[2], al[2]);
                tf32_split(As[buf][ks + t4 + 4][mb + 8], ah[3], al[3]);
#pragma unroll
                for (int nt = 0; nt < 8; nt++) {
                    mma8(acc[mt][nt], ah, bh[nt]);   // hi*hi
                    mma8(acc[mt][nt], ah, bl[nt]);   // hi*lo
                    mma8(acc[mt][nt], al, bh[nt]);   // lo*hi
                }
            }
        }

        if (has_next) {
            const int nb2 = buf ^ 1;
#pragma unroll
            for (int j = 0; j < 2; j++) {
                const int f  = tid * 2 + j;
                const int ml = f >> 2;
                const int k4 = (f & 3) * 4;
                As[nb2][k4 + 0][ml] = a_r[j].x; As[nb2][k4 + 1][ml] = a_r[j].y;
                As[nb2][k4 + 2][ml] = a_r[j].z; As[nb2][k4 + 3][ml] = a_r[j].w;
            }
#pragma unroll
            for (int j = 0; j < 4; j++) {
                const int g  = tid * 4 + j;
                const int kl = g >> 5;
                const int n4 = (g & 31) * 4;
                *(float4*)&Bs[nb2][kl][n4] = b_r[j];
            }
            __syncthreads();
            buf = nb2;
        }
    }

    // ---- epilogue: write C + bias. c-frag: rows gid/gid+8, cols 2*t4, 2*t4+1
#pragma unroll
    for (int mt = 0; mt < 2; mt++) {
#pragma unroll
        for (int nt = 0; nt < 8; nt++) {
            const int row = mG + wm * 32 + mt * 16 + gid;
            const int col = nG + wn * 64 + nt * 8 + t4 * 2;
            const float b0 = bias[col], b1 = bias[col + 1];
            float2 v0 = make_float2(acc[mt][nt][0] + b0, acc[mt][nt][1] + b1);
            float2 v1 = make_float2(acc[mt][nt][2] + b0, acc[mt][nt][3] + b1);
            *(float2*)(C + (size_t)row * DM + col)       = v0;
            *(float2*)(C + (size_t)(row + 8) * DM + col) = v1;
        }
    }
}

// ------------------------- 2) sampled scores -> M metric ---------------------
__global__ __launch_bounds__(256) void sample_score_kernel(const int* __restrict__ sidx)
{
    const int bl = blockIdx.x;
    const int b = bl >> 12;
    const int l = bl & 4095;
    const int w = threadIdx.x >> 5;
    const int lane = threadIdx.x & 31;

    __shared__ int ss[UPART];
    if (threadIdx.x < UPART) ss[threadIdx.x] = sidx[l * UPART + threadIdx.x];
    __syncthreads();

    const float2 qv = ((const float2*)(g_Q + (size_t)bl * DM + w * DH))[lane];
    float mmax = -1e30f, msum = 0.f;
    for (int u = 0; u < UPART; u++) {
        const float2 kv = ((const float2*)(g_K + (size_t)(b * LENC + ss[u]) * DM + w * DH))[lane];
        float v = qv.x * kv.x + qv.y * kv.y;
#pragma unroll
        for (int o = 16; o; o >>= 1) v += __shfl_xor_sync(FULL, v, o);
        mmax = fmaxf(mmax, v);
        msum += v;
    }
    if (lane == 0)
        g_M[((b * NH + w) << 12) + l] = mmax - msum * (1.0f / (float)LENC);
}

// ------------------------- 3) top-45 per (b,h) -------------------------------
__global__ __launch_bounds__(256) void topk_kernel()
{
    const int bh = blockIdx.x;
    const float* Mrow = g_M + bh * LDEC;
    __shared__ float vals[LDEC];
    __shared__ float rv[256];
    __shared__ int ri[256];
    const int tid = threadIdx.x;
    for (int i = tid; i < LDEC; i += 256) vals[i] = Mrow[i];
    __syncthreads();
    for (int t = 0; t < NTOP; t++) {
        float bv = -1e30f; int bi = LDEC;
        for (int i = tid; i < LDEC; i += 256) {
            const float v = vals[i];
            if (v > bv || (v == bv && i < bi)) { bv = v; bi = i; }
        }
        rv[tid] = bv; ri[tid] = bi;
        __syncthreads();
        for (int s = 128; s; s >>= 1) {
            if (tid < s) {
                const float ov = rv[tid + s]; const int oi = ri[tid + s];
                if (ov > rv[tid] || (ov == rv[tid] && oi < ri[tid])) { rv[tid] = ov; ri[tid] = oi; }
            }
            __syncthreads();
        }
        if (tid == 0) {
            g_top[bh * NTOP + t] = ri[0];
            vals[ri[0]] = -1e30f;
        }
        __syncthreads();
    }
}

// ------------------------- 4) sparse attention, split-K partials -------------
// grid (BH, NSPLIT, QSPLIT), 128 threads. 15 queries/block -> QPW2=4 state regs
// per array (was 12) to lift occupancy (was 230 regs / 12.2% occ / 115us).
__global__ __launch_bounds__(128) void attn_partial_kernel()
{
    const int bh = blockIdx.x;
    const int sp = blockIdx.y;
    const int qz = blockIdx.z;
    const int b = bh >> 3, h = bh & 7;
    const int tid = threadIdx.x, w = tid >> 5, lane = tid & 31;

    __shared__ float Qs[QPB][DH];
    __shared__ float Ks[32][65];
    __shared__ float Vs[32][65];

    for (int idx = tid; idx < QPB * 16; idx += 128) {
        const int u = idx >> 4, c4 = idx & 15;
        const int qi = g_top[bh * NTOP + qz * QPB + u];
        *(float4*)&Qs[u][c4 * 4] =
            *(const float4*)(g_Q + (size_t)(b * LDEC + qi) * DM + h * DH + c4 * 4);
    }
    __syncthreads();

    float m[QPW2], lsum[QPW2], acc0[QPW2], acc1[QPW2];
#pragma unroll
    for (int i = 0; i < QPW2; i++) { m[i] = -1e30f; lsum[i] = 0.f; acc0[i] = 0.f; acc1[i] = 0.f; }

    const int kbase = sp * KSEG;
    for (int kt = 0; kt < KSEG; kt += 32) {
        for (int idx = tid; idx < 32 * 16; idx += 128) {
            const int r = idx >> 4, c4 = idx & 15;
            const size_t off = (size_t)(b * LENC + kbase + kt + r) * DM + h * DH + c4 * 4;
            // Ks/Vs rows have stride 65 floats (260B) -> float4 STS would be
            // misaligned on odd rows. Load gmem as float4, store 4 scalars.
            const float4 kv = *(const float4*)(g_K + off);
            const float4 vv = *(const float4*)(g_V + off);
            Ks[r][c4 * 4 + 0] = kv.x; Ks[r][c4 * 4 + 1] = kv.y;
            Ks[r][c4 * 4 + 2] = kv.z; Ks[r][c4 * 4 + 3] = kv.w;
            Vs[r][c4 * 4 + 0] = vv.x; Vs[r][c4 * 4 + 1] = vv.y;
            Vs[r][c4 * 4 + 2] = vv.z; Vs[r][c4 * 4 + 3] = vv.w;
        }
        __syncthreads();
#pragma unroll
        for (int qq = 0; qq < QPW2; qq++) {
            const int ul = w + qq * 4;
            if (ul < QPB) {
                float s = 0.f;
#pragma unroll
                for (int d = 0; d < DH; d++) s = fmaf(Qs[ul][d], Ks[lane][d], s);
                s *= 0.125f;   // 1/sqrt(64)
                float tm = s;
#pragma unroll
                for (int o = 16; o; o >>= 1) tm = fmaxf(tm, __shfl_xor_sync(FULL, tm, o));
                const float nm = fmaxf(m[qq], tm);
                const float scale = __expf(m[qq] - nm);
                const float p = __expf(s - nm);
                float ps = p;
#pragma unroll
                for (int o = 16; o; o >>= 1) ps += __shfl_xor_sync(FULL, ps, o);
                lsum[qq] = lsum[qq] * scale + ps;
                acc0[qq] *= scale; acc1[qq] *= scale;
                m[qq] = nm;
#pragma unroll
                for (int j = 0; j < 32; j++) {
                    const float pj = __shfl_sync(FULL, p, j);
                    acc0[qq] = fmaf(pj, Vs[j][lane], acc0[qq]);
                    acc1[qq] = fmaf(pj, Vs[j][lane + 32], acc1[qq]);
                }
            }
        }
        __syncthreads();
    }
#pragma unroll
    for (int qq = 0; qq < QPW2; qq++) {
        const int ul = w + qq * 4;
        if (ul < QPB) {
            const int ug = qz * QPB + ul;
            const int base = (bh * NSPLIT + sp) * NTOP + ug;
            if (lane == 0) { g_pm[base] = m[qq]; g_pl[base] = lsum[qq]; }
            g_pacc[(size_t)base * DH + lane]      = acc0[qq];
            g_pacc[(size_t)base * DH + lane + 32] = acc1[qq];
        }
    }
}

// ------------------------- 5) combine split-K partials -----------------------
__global__ __launch_bounds__(256) void attn_combine_kernel()
{
    const int bh = blockIdx.x;
    const int w = threadIdx.x >> 5, lane = threadIdx.x & 31;
    for (int u = w; u < NTOP; u += 8) {
        float mg = -1e30f;
        if (lane < NSPLIT) mg = g_pm[(bh * NSPLIT + lane) * NTOP + u];
#pragma unroll
        for (int o = 16; o; o >>= 1) mg = fmaxf(mg, __shfl_xor_sync(FULL, mg, o));
        float lg = 0.f;
        if (lane < NSPLIT)
            lg = g_pl[(bh * NSPLIT + lane) * NTOP + u] *
                 __expf(g_pm[(bh * NSPLIT + lane) * NTOP + u] - mg);
#pragma unroll
        for (int o = 16; o; o >>= 1) lg += __shfl_xor_sync(FULL, lg, o);
        float a0 = 0.f, a1 = 0.f;
        for (int s = 0; s < NSPLIT; s++) {
            const int base = (bh * NSPLIT + s) * NTOP + u;
            const float wgt = __expf(g_pm[base] - mg);
            a0 = fmaf(wgt, g_pacc[(size_t)base * DH + lane], a0);
            a1 = fmaf(wgt, g_pacc[(size_t)base * DH + lane + 32], a1);
        }
        const float inv = 1.0f / lg;
        g_upd[(bh * NTOP + u) * DH + lane]      = a0 * inv;
        g_upd[(bh * NTOP + u) * DH + lane + 32] = a1 * inv;
    }
}

// ------------------------- 6) V column sums (deterministic 2-stage) ----------
__global__ __launch_bounds__(512) void vmean_part_kernel()
{
    const int b = blockIdx.x >> 5;
    const int chunk = blockIdx.x & 31;
    const int c = threadIdx.x;
    const float* base = g_V + (size_t)(b * LENC + chunk * 128) * DM + c;
    float s = 0.f;
#pragma unroll 4
    for (int r = 0; r < 128; r++) s += base[(size_t)r * DM];
    g_vpart[blockIdx.x * DM + c] = s;
}

__global__ __launch_bounds__(512) void vmean_final_kernel()
{
    const int b = blockIdx.x;
    const int c = threadIdx.x;
    float s = 0.f;
#pragma unroll
    for (int k = 0; k < 32; k++) s += g_vpart[(b * 32 + k) * DM + c];
    g_vmean[b * DM + c] = s;
}

// ------------------------- 7) base row: (Vmean cat) @ Wo + bo ----------------
__global__ __launch_bounds__(512) void base_out_kernel(const float* __restrict__ Wo,
                                                       const float* __restrict__ bo)
{
    const int b = blockIdx.x;
    const int j = threadIdx.x;
    __shared__ float vm[DM];
    vm[j] = g_vmean[b * DM + j] * (1.0f / (float)LENC);
    __syncthreads();
    float acc = bo[j];
    for (int k = 0; k < DM; k++) acc = fmaf(vm[k], Wo[(size_t)k * DM + j], acc);
    g_base[b * DM + j] = acc;
}

// ------------------------- 8) broadcast-fill output --------------------------
__global__ __launch_bounds__(256) void fill_kernel(float* __restrict__ out)
{
    const size_t i = (size_t)blockIdx.x * 256 + threadIdx.x;  // float4 index
    const int j4 = (int)(i & 127);            // 128 float4 per row
    const size_t row = i >> 7;                // b*LDEC + l
    const int b = (int)(row >> 12);
    ((float4*)out)[i] = *(const float4*)&g_base[b * DM + j4 * 4];
}

// ------------------------- 9) rank-64 row corrections (per head, race-free) --
__global__ __launch_bounds__(256) void delta_kernel(int h, const float* __restrict__ Wo,
                                                    float* __restrict__ out)
{
    const int g = blockIdx.x;       // 0 .. NB*NTOP-1
    const int b = g / NTOP;
    const int u = g % NTOP;
    const int bh = b * NH + h;
    __shared__ float dv[DH];
    const int tid = threadIdx.x;
    if (tid < DH)
        dv[tid] = g_upd[(bh * NTOP + u) * DH + tid] -
                  g_vmean[b * DM + h * DH + tid] * (1.0f / (float)LENC);
    __syncthreads();
    const int row = g_top[bh * NTOP + u];
    float* orow = out + (size_t)(b * LDEC + row) * DM;
    for (int j = tid; j < DM; j += 256) {
        float acc = 0.f;
#pragma unroll
        for (int k = 0; k < DH; k++)
            acc = fmaf(dv[k], Wo[(size_t)(h * DH + k) * DM + j], acc);
        orow[j] += acc;   // distinct rows within one head -> no race
    }
}

// ------------------------- launcher ------------------------------------------
extern "C" void kernel_launch(void* const* d_in, const int* in_sizes, int n_in,
                              void* d_out, int out_size)
{
    const float* x       = (const float*)d_in[0];
    const float* context = (const float*)d_in[1];
    const float* Wq      = (const float*)d_in[2];
    const float* bq      = (const float*)d_in[3];
    const float* Wk      = (const float*)d_in[4];
    const float* bk      = (const float*)d_in[5];
    const float* Wv      = (const float*)d_in[6];
    const float* bv      = (const float*)d_in[7];
    const float* Wo      = (const float*)d_in[8];
    const float* bo      = (const float*)d_in[9];
    const int*   sidx    = (const int*)d_in[10];
    float* out = (float*)d_out;

    dim3 ggrid(DM / 128, GM / 64, 3);        // (4, 256, 3)
    qkv_gemm_tf32<<<ggrid, 128>>>(x, context, Wq, Wk, Wv, bq, bk, bv);

    sample_score_kernel<<<NB * LDEC, 256>>>(sidx);
    topk_kernel<<<BH, 256>>>();

    attn_partial_kernel<<<dim3(BH, NSPLIT, QSPLIT), 128>>>();
    attn_combine_kernel<<<BH, 256>>>();

    vmean_part_kernel<<<NB * 32, 512>>>();
    vmean_final_kernel<<<NB, 512>>>();
    base_out_kernel<<<NB, 512>>>(Wo, bo);

    fill_kernel<<<(GM * DM / 4) / 256, 256>>>(out);
    for (int h = 0; h < NH; h++)
        delta_kernel<<<NB * NTOP, 256>>>(h, Wo, out);
}